// round 1
// baseline (speedup 1.0000x reference)
#include <cuda_runtime.h>
#include <cstdint>

#define HID     100
#define MCAND   50
#define NTOP    32
#define NITER   100
#define NBATCH  4096
#define RPC     3          // rows (batch elements) per CTA
#define TPB     160        // 3*50 active lanes + 10 idle

// ---------------------------------------------------------------------------
// Threefry-2x32 (20 rounds), identical to jax._src.prng
// ---------------------------------------------------------------------------
__device__ __forceinline__ void tf2x32(uint32_t k0, uint32_t k1,
                                       uint32_t x0, uint32_t x1,
                                       uint32_t &o0, uint32_t &o1) {
  uint32_t ks2 = k0 ^ k1 ^ 0x1BD11BDAu;
#define TFROT(r) { x0 += x1; x1 = __funnelshift_l(x1, x1, (r)); x1 ^= x0; }
  x0 += k0; x1 += k1;
  TFROT(13) TFROT(15) TFROT(26) TFROT(6)
  x0 += k1;  x1 += ks2 + 1u;
  TFROT(17) TFROT(29) TFROT(16) TFROT(24)
  x0 += ks2; x1 += k0 + 2u;
  TFROT(13) TFROT(15) TFROT(26) TFROT(6)
  x0 += k0;  x1 += k1 + 3u;
  TFROT(17) TFROT(29) TFROT(16) TFROT(24)
  x0 += k1;  x1 += ks2 + 4u;
  TFROT(13) TFROT(15) TFROT(26) TFROT(6)
  x0 += ks2; x1 += k0 + 5u;
#undef TFROT
  o0 = x0; o1 = x1;
}

// jax partitionable random_bits: element idx -> threefry(key, hi=0, lo=idx), xor-fold
__device__ __forceinline__ uint32_t jax_bits(uint32_t ka, uint32_t kb, uint32_t idx) {
  uint32_t o0, o1;
  tf2x32(ka, kb, 0u, idx, o0, o1);
  return o0 ^ o1;
}

__device__ __forceinline__ float u01_from_bits(uint32_t bits) {
  return __uint_as_float((bits >> 9) | 0x3F800000u) - 1.0f;
}

// XLA ErfInv32 (Giles) polynomial — matches lax.erf_inv lowering
__device__ __forceinline__ float erfinv_f32(float x) {
  float w = -log1pf(-x * x);
  float p;
  if (w < 5.0f) {
    w -= 2.5f;
    p = 2.81022636e-08f;
    p = fmaf(p, w, 3.43273939e-07f);
    p = fmaf(p, w, -3.5233877e-06f);
    p = fmaf(p, w, -4.39150654e-06f);
    p = fmaf(p, w, 0.00021858087f);
    p = fmaf(p, w, -0.00125372503f);
    p = fmaf(p, w, -0.00417768164f);
    p = fmaf(p, w, 0.246640727f);
    p = fmaf(p, w, 1.50140941f);
  } else {
    w = sqrtf(w) - 3.0f;
    p = -0.000200214257f;
    p = fmaf(p, w, 0.000100950558f);
    p = fmaf(p, w, 0.00134934322f);
    p = fmaf(p, w, -0.00367342844f);
    p = fmaf(p, w, 0.00573950773f);
    p = fmaf(p, w, -0.0076224613f);
    p = fmaf(p, w, 0.00943887047f);
    p = fmaf(p, w, 1.00167406f);
    p = fmaf(p, w, 2.83297682f);
  }
  return p * x;
}

// ---------------------------------------------------------------------------
// Persistent CEM kernel: each CTA owns RPC batch rows for all 100 iterations.
// Layer-2 GEMV uses packed fp32 FFMA2 (fma.rn.f32x2) with W2 broadcast from SMEM.
// ---------------------------------------------------------------------------
__global__ void __launch_bounds__(TPB, 2) cem_kernel(
    const float* __restrict__ states, const float* __restrict__ W1,
    const float* __restrict__ b1,     const float* __restrict__ W2,
    const float* __restrict__ b2,     const float* __restrict__ W3,
    const float* __restrict__ b3,     float* __restrict__ out) {

  __shared__ __align__(16) float w2_s[HID * HID];   // [k][j] row-major (as input)
  __shared__ float2 rowdat[RPC][HID];               // (.x = s0*W1_0+s1*W1_1+b1, .y = W1_2)
  __shared__ float  b2_s[HID];
  __shared__ float  w3_s[HID];
  __shared__ float  qs[RPC][MCAND];
  __shared__ float  mu_s[RPC];
  __shared__ float  sd_s[RPC];
  __shared__ uint32_t keyA[NITER - 1];
  __shared__ uint32_t keyB[NITER - 1];

  const int tid  = threadIdx.x;
  const int cta  = blockIdx.x;
  int row        = tid / MCAND;          // 0..2 (garbage for tid>=150)
  const int cand = tid - row * MCAND;
  bool active    = (tid < RPC * MCAND);
  int grow       = cta * RPC + row;
  if (grow >= NBATCH) active = false;
  const int rowc = active ? row : 0;     // safe smem row for idle lanes

  // ---- cooperative weight staging ----
  for (int i = tid; i < HID * HID; i += TPB) w2_s[i] = W2[i];
  for (int i = tid; i < HID; i += TPB) { b2_s[i] = b2[i]; w3_s[i] = W3[i]; }
  for (int i = tid; i < RPC * HID; i += TPB) {
    int r = i / HID, k = i - r * HID;
    int gr = cta * RPC + r;
    float s0 = 0.f, s1 = 0.f;
    if (gr < NBATCH) { s0 = states[2 * gr]; s1 = states[2 * gr + 1]; }
    rowdat[r][k] = make_float2(fmaf(s1, W1[HID + k], fmaf(s0, W1[k], b1[k])),
                               W1[2 * HID + k]);
  }
  const float b3v = b3[0];

  // ---- PRNG setup: key = jax.random.key(42) => (0, 42); partitionable split ----
  uint32_t k0a, k0b, klA, klB;
  tf2x32(0u, 42u, 0u, 0u, k0a, k0b);   // k0    = split(key)[0]
  tf2x32(0u, 42u, 0u, 1u, klA, klB);   // kloop = split(key)[1]
  if (tid < NITER - 1) {               // keys = split(kloop, 99): keys[i] = tf(kloop,0,i)
    uint32_t ya, yb;
    tf2x32(klA, klB, 0u, (uint32_t)tid, ya, yb);
    keyA[tid] = ya; keyB[tid] = yb;
  }
  __syncthreads();

  // ---- iteration 0 angles: uniform [0,1) ----
  const uint32_t idx = active ? (uint32_t)(grow * MCAND + cand) : 0u;
  float angle = u01_from_bits(jax_bits(k0a, k0b, idx));

  const float LO     = __uint_as_float(0xBF7FFFFFu);  // nextafter(-1,0)
  const float SQRT2  = __uint_as_float(0x3FB504F3u);
  const float TWOPI  = __uint_as_float(0x40C90FDBu);
  const int wid = tid >> 5, lane = tid & 31;
  const int nrows = min(RPC, NBATCH - cta * RPC);
  const float2* rd = &rowdat[rowc][0];

  for (int it = 0; it < NITER - 1; ++it) {
    // ================= qnet eval (dominant loop) =================
    unsigned long long acc[HID / 2];
#pragma unroll
    for (int j = 0; j < HID / 2; ++j) acc[j] = 0ull;

#pragma unroll 2
    for (int k = 0; k < HID; ++k) {
      float2 bw = rd[k];                                   // (base, W1 angle col)
      float h = fmaxf(fmaf(angle, bw.y, bw.x), 0.0f);      // layer-1 fused
      unsigned long long hh;
      asm("mov.b64 %0, {%1, %1};" : "=l"(hh) : "f"(h));
      const ulonglong2* w2v = reinterpret_cast<const ulonglong2*>(w2_s + k * HID);
#pragma unroll
      for (int j4 = 0; j4 < HID / 4; ++j4) {
        ulonglong2 w = w2v[j4];                            // LDS.128, warp-broadcast
        asm("fma.rn.f32x2 %0, %1, %2, %0;" : "+l"(acc[2 * j4])     : "l"(w.x), "l"(hh));
        asm("fma.rn.f32x2 %0, %1, %2, %0;" : "+l"(acc[2 * j4 + 1]) : "l"(w.y), "l"(hh));
      }
    }
    float q = b3v;
#pragma unroll
    for (int jp = 0; jp < HID / 2; ++jp) {
      float e0, e1;
      asm("mov.b64 {%0, %1}, %2;" : "=f"(e0), "=f"(e1) : "l"(acc[jp]));
      q = fmaf(fmaxf(e0 + b2_s[2 * jp],     0.f), w3_s[2 * jp],     q);
      q = fmaf(fmaxf(e1 + b2_s[2 * jp + 1], 0.f), w3_s[2 * jp + 1], q);
    }
    if (active) qs[row][cand] = q;
    __syncthreads();

    // ========== per-row top-32 stats (warp r handles row r) ==========
    if (wid < nrows) {
      const int r = wid;
      const bool has2 = lane < (MCAND - 32);               // lanes 0..17 own a 2nd cand
      const float q1 = qs[r][lane];
      const float q2 = qs[r][has2 ? 32 + lane : 0];
      int rank1 = 0, rank2 = 0;
#pragma unroll
      for (int c = 0; c < MCAND; ++c) {
        float qv = qs[r][c];
        rank1 += (qv > q1) || (qv == q1 && c < lane);
        rank2 += (qv > q2) || (qv == q2 && c < 32 + lane);
      }
      const bool s1 = rank1 < NTOP;
      const bool s2 = has2 && (rank2 < NTOP);
      float s = (s1 ? q1 : 0.f) + (s2 ? q2 : 0.f);
#pragma unroll
      for (int o = 16; o > 0; o >>= 1) s += __shfl_xor_sync(0xffffffffu, s, o);
      const float mu = s * (1.0f / NTOP);
      float d = (s1 ? (q1 - mu) * (q1 - mu) : 0.f) + (s2 ? (q2 - mu) * (q2 - mu) : 0.f);
#pragma unroll
      for (int o = 16; o > 0; o >>= 1) d += __shfl_xor_sync(0xffffffffu, d, o);
      if (lane == 0) { mu_s[r] = mu; sd_s[r] = sqrtf(d * (1.0f / (NTOP - 1))); }
    }
    __syncthreads();

    if (it == NITER - 2) {
      if (active && cand == 0) out[grow] = mu_s[row] * TWOPI;
      break;
    }

    // ========== sample next angles: N(mu_q, std_q) via jax normal ==========
    {
      uint32_t bits = jax_bits(keyA[it], keyB[it], idx);
      float u = fmaxf(LO, fmaf(u01_from_bits(bits), 2.0f, LO));
      float eps = SQRT2 * erfinv_f32(u);
      angle = fmaf(sd_s[rowc], eps, mu_s[rowc]);
    }
  }
}

extern "C" void kernel_launch(void* const* d_in, const int* in_sizes, int n_in,
                              void* d_out, int out_size) {
  const float* states = (const float*)d_in[0];
  const float* W1     = (const float*)d_in[1];
  const float* b1     = (const float*)d_in[2];
  const float* W2     = (const float*)d_in[3];
  const float* b2     = (const float*)d_in[4];
  const float* W3     = (const float*)d_in[5];
  const float* b3     = (const float*)d_in[6];
  float* out          = (float*)d_out;
  (void)in_sizes; (void)n_in; (void)out_size;

  const int nCTA = (NBATCH + RPC - 1) / RPC;   // 1366
  cem_kernel<<<nCTA, TPB>>>(states, W1, b1, W2, b2, W3, b3, out);
}

// round 2
// speedup vs baseline: 1.2452x; 1.2452x over previous
#include <cuda_runtime.h>
#include <cstdint>

#define HID     100
#define MCAND   50
#define NTOP    32
#define NITER   100
#define NBATCH  4096
#define RPC     3          // rows (batch elements) per CTA
#define TPB     160        // 3*50 active lanes + 10 idle
#define NSL     5          // j-slices per candidate group
#define NCC     5          // candidates per thread
#define JSL     (HID / NSL)   // 20 outputs per slice

// ---------------------------------------------------------------------------
// Threefry-2x32 (20 rounds), identical to jax._src.prng
// ---------------------------------------------------------------------------
__device__ __forceinline__ void tf2x32(uint32_t k0, uint32_t k1,
                                       uint32_t x0, uint32_t x1,
                                       uint32_t &o0, uint32_t &o1) {
  uint32_t ks2 = k0 ^ k1 ^ 0x1BD11BDAu;
#define TFROT(r) { x0 += x1; x1 = __funnelshift_l(x1, x1, (r)); x1 ^= x0; }
  x0 += k0; x1 += k1;
  TFROT(13) TFROT(15) TFROT(26) TFROT(6)
  x0 += k1;  x1 += ks2 + 1u;
  TFROT(17) TFROT(29) TFROT(16) TFROT(24)
  x0 += ks2; x1 += k0 + 2u;
  TFROT(13) TFROT(15) TFROT(26) TFROT(6)
  x0 += k0;  x1 += k1 + 3u;
  TFROT(17) TFROT(29) TFROT(16) TFROT(24)
  x0 += k1;  x1 += ks2 + 4u;
  TFROT(13) TFROT(15) TFROT(26) TFROT(6)
  x0 += ks2; x1 += k0 + 5u;
#undef TFROT
  o0 = x0; o1 = x1;
}

__device__ __forceinline__ uint32_t jax_bits(uint32_t ka, uint32_t kb, uint32_t idx) {
  uint32_t o0, o1;
  tf2x32(ka, kb, 0u, idx, o0, o1);
  return o0 ^ o1;
}

__device__ __forceinline__ float u01_from_bits(uint32_t bits) {
  return __uint_as_float((bits >> 9) | 0x3F800000u) - 1.0f;
}

// XLA ErfInv32 (Giles) polynomial — matches lax.erf_inv lowering
__device__ __forceinline__ float erfinv_f32(float x) {
  float w = -log1pf(-x * x);
  float p;
  if (w < 5.0f) {
    w -= 2.5f;
    p = 2.81022636e-08f;
    p = fmaf(p, w, 3.43273939e-07f);
    p = fmaf(p, w, -3.5233877e-06f);
    p = fmaf(p, w, -4.39150654e-06f);
    p = fmaf(p, w, 0.00021858087f);
    p = fmaf(p, w, -0.00125372503f);
    p = fmaf(p, w, -0.00417768164f);
    p = fmaf(p, w, 0.246640727f);
    p = fmaf(p, w, 1.50140941f);
  } else {
    w = sqrtf(w) - 3.0f;
    p = -0.000200214257f;
    p = fmaf(p, w, 0.000100950558f);
    p = fmaf(p, w, 0.00134934322f);
    p = fmaf(p, w, -0.00367342844f);
    p = fmaf(p, w, 0.00573950773f);
    p = fmaf(p, w, -0.0076224613f);
    p = fmaf(p, w, 0.00943887047f);
    p = fmaf(p, w, 1.00167406f);
    p = fmaf(p, w, 2.83297682f);
  }
  return p * x;
}

// ---------------------------------------------------------------------------
// Persistent CEM kernel. Thread (row, grp, sl) computes, for 5 candidates
// {5*grp..5*grp+4}, the j-slice [20*sl, 20*sl+20) of the hidden layer.
// W2 shared loads are reused 5x across candidates -> L1 traffic / FMA = 1/5.
// ---------------------------------------------------------------------------
__global__ void __launch_bounds__(TPB, 2) cem_kernel(
    const float* __restrict__ states, const float* __restrict__ W1,
    const float* __restrict__ b1,     const float* __restrict__ W2,
    const float* __restrict__ b2,     const float* __restrict__ W3,
    const float* __restrict__ b3,     float* __restrict__ out) {

  __shared__ __align__(16) float w2_s[HID * HID];   // [k][j] row-major
  __shared__ float2 rowdat[RPC][HID];               // (.x = s0*W1_0+s1*W1_1+b1, .y = W1_2)
  __shared__ float  b2_s[HID];
  __shared__ float  w3_s[HID];
  __shared__ float  qs[RPC][MCAND];
  __shared__ float  qpart[RPC][MCAND][NSL];
  __shared__ float  angles_s[RPC][MCAND];
  __shared__ float  mu_s[RPC];
  __shared__ float  sd_s[RPC];
  __shared__ uint32_t keyA[NITER - 1];
  __shared__ uint32_t keyB[NITER - 1];

  const int tid  = threadIdx.x;
  const int cta  = blockIdx.x;
  int row        = tid / MCAND;          // 0..2 (garbage for tid>=150)
  const int cin  = tid - row * MCAND;    // owned candidate index 0..49
  const int grp  = cin / NCC;            // 0..9
  const int sl   = cin - grp * NCC;      // 0..4
  bool active    = (tid < RPC * MCAND);
  int grow       = cta * RPC + row;
  if (grow >= NBATCH) active = false;
  const int rowc = active ? row : 0;     // safe smem row for idle lanes

  // ---- cooperative weight staging ----
  for (int i = tid; i < HID * HID; i += TPB) w2_s[i] = W2[i];
  for (int i = tid; i < HID; i += TPB) { b2_s[i] = b2[i]; w3_s[i] = W3[i]; }
  for (int i = tid; i < RPC * HID; i += TPB) {
    int r = i / HID, k = i - r * HID;
    int gr = cta * RPC + r;
    float s0 = 0.f, s1 = 0.f;
    if (gr < NBATCH) { s0 = states[2 * gr]; s1 = states[2 * gr + 1]; }
    rowdat[r][k] = make_float2(fmaf(s1, W1[HID + k], fmaf(s0, W1[k], b1[k])),
                               W1[2 * HID + k]);
  }
  const float b3v = b3[0];

  // ---- PRNG setup: key = jax.random.key(42) => (0, 42); partitionable split ----
  uint32_t k0a, k0b, klA, klB;
  tf2x32(0u, 42u, 0u, 0u, k0a, k0b);   // k0    = split(key)[0]
  tf2x32(0u, 42u, 0u, 1u, klA, klB);   // kloop = split(key)[1]
  if (tid < NITER - 1) {
    uint32_t ya, yb;
    tf2x32(klA, klB, 0u, (uint32_t)tid, ya, yb);
    keyA[tid] = ya; keyB[tid] = yb;
  }

  // ---- iteration 0 angles: uniform [0,1), written by owner thread ----
  const uint32_t idx = active ? (uint32_t)(grow * MCAND + cin) : 0u;
  if (active) angles_s[row][cin] = u01_from_bits(jax_bits(k0a, k0b, idx));

  const float LO     = __uint_as_float(0xBF7FFFFFu);  // nextafter(-1,0)
  const float SQRT2  = __uint_as_float(0x3FB504F3u);
  const float TWOPI  = __uint_as_float(0x40C90FDBu);
  const int wid = tid >> 5, lane = tid & 31;
  const int nrows = min(RPC, NBATCH - cta * RPC);
  const float2* rd = &rowdat[rowc][0];
  const float* w2base = w2_s + sl * JSL;
  __syncthreads();

  for (int it = 0; it < NITER - 1; ++it) {
    // ---- fetch my 5 candidates' angles ----
    float ang[NCC];
#pragma unroll
    for (int cc = 0; cc < NCC; ++cc) ang[cc] = angles_s[rowc][grp * NCC + cc];

    // ================= qnet eval (dominant loop) =================
    unsigned long long acc[NCC * JSL / 2];   // 5 cand x 10 packed pairs
#pragma unroll
    for (int i = 0; i < NCC * JSL / 2; ++i) acc[i] = 0ull;

    const float* w2p = w2base;
#pragma unroll 2
    for (int k = 0; k < HID; ++k) {
      float2 bw = rd[k];                                 // (base, W1 angle col)
      ulonglong2 wa = *reinterpret_cast<const ulonglong2*>(w2p);
      ulonglong2 wb = *reinterpret_cast<const ulonglong2*>(w2p + 4);
      ulonglong2 wc = *reinterpret_cast<const ulonglong2*>(w2p + 8);
      ulonglong2 wd = *reinterpret_cast<const ulonglong2*>(w2p + 12);
      ulonglong2 we = *reinterpret_cast<const ulonglong2*>(w2p + 16);
#pragma unroll
      for (int cc = 0; cc < NCC; ++cc) {
        float h = fmaxf(fmaf(ang[cc], bw.y, bw.x), 0.0f);
        unsigned long long hh;
        asm("mov.b64 %0, {%1, %1};" : "=l"(hh) : "f"(h));
        unsigned long long* a = acc + cc * (JSL / 2);
        asm("fma.rn.f32x2 %0, %1, %2, %0;" : "+l"(a[0]) : "l"(wa.x), "l"(hh));
        asm("fma.rn.f32x2 %0, %1, %2, %0;" : "+l"(a[1]) : "l"(wa.y), "l"(hh));
        asm("fma.rn.f32x2 %0, %1, %2, %0;" : "+l"(a[2]) : "l"(wb.x), "l"(hh));
        asm("fma.rn.f32x2 %0, %1, %2, %0;" : "+l"(a[3]) : "l"(wb.y), "l"(hh));
        asm("fma.rn.f32x2 %0, %1, %2, %0;" : "+l"(a[4]) : "l"(wc.x), "l"(hh));
        asm("fma.rn.f32x2 %0, %1, %2, %0;" : "+l"(a[5]) : "l"(wc.y), "l"(hh));
        asm("fma.rn.f32x2 %0, %1, %2, %0;" : "+l"(a[6]) : "l"(wd.x), "l"(hh));
        asm("fma.rn.f32x2 %0, %1, %2, %0;" : "+l"(a[7]) : "l"(wd.y), "l"(hh));
        asm("fma.rn.f32x2 %0, %1, %2, %0;" : "+l"(a[8]) : "l"(we.x), "l"(hh));
        asm("fma.rn.f32x2 %0, %1, %2, %0;" : "+l"(a[9]) : "l"(we.y), "l"(hh));
      }
      w2p += HID;
    }

    // ---- layer 2 bias+relu, layer 3 partial dot over my j-slice ----
#pragma unroll
    for (int cc = 0; cc < NCC; ++cc) {
      float q = 0.0f;
#pragma unroll
      for (int jp = 0; jp < JSL / 2; ++jp) {
        float e0, e1;
        asm("mov.b64 {%0, %1}, %2;" : "=f"(e0), "=f"(e1) : "l"(acc[cc * (JSL / 2) + jp]));
        const int j = sl * JSL + 2 * jp;
        q = fmaf(fmaxf(e0 + b2_s[j],     0.f), w3_s[j],     q);
        q = fmaf(fmaxf(e1 + b2_s[j + 1], 0.f), w3_s[j + 1], q);
      }
      if (active) qpart[row][grp * NCC + cc][sl] = q;
    }
    __syncthreads();

    // ---- owner thread reduces 5 slice partials for its candidate ----
    if (active) {
      float q = b3v;
#pragma unroll
      for (int s2 = 0; s2 < NSL; ++s2) q += qpart[row][cin][s2];
      qs[row][cin] = q;
    }
    __syncthreads();

    // ========== per-row top-32 stats (warp r handles row r) ==========
    if (wid < nrows) {
      const int r = wid;
      const bool has2 = lane < (MCAND - 32);
      const float q1 = qs[r][lane];
      const float q2 = qs[r][has2 ? 32 + lane : 0];
      int rank1 = 0, rank2 = 0;
#pragma unroll
      for (int c = 0; c < MCAND; ++c) {
        float qv = qs[r][c];
        rank1 += (qv > q1) || (qv == q1 && c < lane);
        rank2 += (qv > q2) || (qv == q2 && c < 32 + lane);
      }
      const bool s1 = rank1 < NTOP;
      const bool s2 = has2 && (rank2 < NTOP);
      float s = (s1 ? q1 : 0.f) + (s2 ? q2 : 0.f);
#pragma unroll
      for (int o = 16; o > 0; o >>= 1) s += __shfl_xor_sync(0xffffffffu, s, o);
      const float mu = s * (1.0f / NTOP);
      float d = (s1 ? (q1 - mu) * (q1 - mu) : 0.f) + (s2 ? (q2 - mu) * (q2 - mu) : 0.f);
#pragma unroll
      for (int o = 16; o > 0; o >>= 1) d += __shfl_xor_sync(0xffffffffu, d, o);
      if (lane == 0) { mu_s[r] = mu; sd_s[r] = sqrtf(d * (1.0f / (NTOP - 1))); }
    }
    __syncthreads();

    if (it == NITER - 2) {
      if (active && cin == 0) out[grow] = mu_s[row] * TWOPI;
      break;
    }

    // ---- sample next angles: N(mu_q, std_q), owner thread only ----
    if (active) {
      uint32_t bits = jax_bits(keyA[it], keyB[it], idx);
      float u = fmaxf(LO, fmaf(u01_from_bits(bits), 2.0f, LO));
      angles_s[row][cin] = fmaf(sd_s[row], SQRT2 * erfinv_f32(u), mu_s[row]);
    }
    __syncthreads();
  }
}

extern "C" void kernel_launch(void* const* d_in, const int* in_sizes, int n_in,
                              void* d_out, int out_size) {
  const float* states = (const float*)d_in[0];
  const float* W1     = (const float*)d_in[1];
  const float* b1     = (const float*)d_in[2];
  const float* W2     = (const float*)d_in[3];
  const float* b2     = (const float*)d_in[4];
  const float* W3     = (const float*)d_in[5];
  const float* b3     = (const float*)d_in[6];
  float* out          = (float*)d_out;
  (void)in_sizes; (void)n_in; (void)out_size;

  const int nCTA = (NBATCH + RPC - 1) / RPC;   // 1366
  cem_kernel<<<nCTA, TPB>>>(states, W1, b1, W2, b2, W3, b3, out);
}

// round 4
// speedup vs baseline: 5.8366x; 4.6875x over previous
#include <cuda_runtime.h>
#include <cstdint>

#define HID     100
#define NREG    (HID + 1)
#define MCAND   50
#define NTOP    32
#define NITER   100
#define NBATCH  4096
#define TPB     128

// ---------------------------------------------------------------------------
// Threefry-2x32 (20 rounds), identical to jax._src.prng
// ---------------------------------------------------------------------------
__device__ __forceinline__ void tf2x32(uint32_t k0, uint32_t k1,
                                       uint32_t x0, uint32_t x1,
                                       uint32_t &o0, uint32_t &o1) {
  uint32_t ks2 = k0 ^ k1 ^ 0x1BD11BDAu;
#define TFROT(r) { x0 += x1; x1 = __funnelshift_l(x1, x1, (r)); x1 ^= x0; }
  x0 += k0; x1 += k1;
  TFROT(13) TFROT(15) TFROT(26) TFROT(6)
  x0 += k1;  x1 += ks2 + 1u;
  TFROT(17) TFROT(29) TFROT(16) TFROT(24)
  x0 += ks2; x1 += k0 + 2u;
  TFROT(13) TFROT(15) TFROT(26) TFROT(6)
  x0 += k0;  x1 += k1 + 3u;
  TFROT(17) TFROT(29) TFROT(16) TFROT(24)
  x0 += k1;  x1 += ks2 + 4u;
  TFROT(13) TFROT(15) TFROT(26) TFROT(6)
  x0 += ks2; x1 += k0 + 5u;
#undef TFROT
  o0 = x0; o1 = x1;
}

__device__ __forceinline__ uint32_t jax_bits(uint32_t ka, uint32_t kb, uint32_t idx) {
  uint32_t o0, o1;
  tf2x32(ka, kb, 0u, idx, o0, o1);
  return o0 ^ o1;
}

__device__ __forceinline__ float u01_from_bits(uint32_t bits) {
  return __uint_as_float((bits >> 9) | 0x3F800000u) - 1.0f;
}

// XLA ErfInv32 (Giles) polynomial — matches lax.erf_inv lowering
__device__ __forceinline__ float erfinv_f32(float x) {
  float w = -log1pf(-x * x);
  float p;
  if (w < 5.0f) {
    w -= 2.5f;
    p = 2.81022636e-08f;
    p = fmaf(p, w, 3.43273939e-07f);
    p = fmaf(p, w, -3.5233877e-06f);
    p = fmaf(p, w, -4.39150654e-06f);
    p = fmaf(p, w, 0.00021858087f);
    p = fmaf(p, w, -0.00125372503f);
    p = fmaf(p, w, -0.00417768164f);
    p = fmaf(p, w, 0.246640727f);
    p = fmaf(p, w, 1.50140941f);
  } else {
    w = sqrtf(w) - 3.0f;
    p = -0.000200214257f;
    p = fmaf(p, w, 0.000100950558f);
    p = fmaf(p, w, 0.00134934322f);
    p = fmaf(p, w, -0.00367342844f);
    p = fmaf(p, w, 0.00573950773f);
    p = fmaf(p, w, -0.0076224613f);
    p = fmaf(p, w, 0.00943887047f);
    p = fmaf(p, w, 1.00167406f);
    p = fmaf(p, w, 2.83297682f);
  }
  return p * x;
}

// ---------------------------------------------------------------------------
// Piecewise-linear CEM kernel. One CTA per batch row.
// h_k(angle) = relu(a_k + b_k*angle) is PWL in angle with knee t_k = -a_k/b_k
// (a_k, b_k fixed per row). Precompute e_j(angle) = A[r][j] + B[r][j]*angle
// per sorted-knee region r. Each candidate eval is then O(HID), not O(HID^2).
// ---------------------------------------------------------------------------
__global__ void __launch_bounds__(TPB, 2) cem_kernel(
    const float* __restrict__ states, const float* __restrict__ W1,
    const float* __restrict__ b1,     const float* __restrict__ W2,
    const float* __restrict__ b2,     const float* __restrict__ W3,
    const float* __restrict__ b3,     float* __restrict__ out) {

  extern __shared__ __align__(16) char smraw[];
  float2*   AB    = reinterpret_cast<float2*>(smraw);          // [NREG][HID]
  float*    tsort = reinterpret_cast<float*>(AB + NREG * HID); // [HID+1] (+inf sentinel)
  float*    tun   = tsort + (HID + 1);                          // [HID]
  float*    a_arr = tun + HID;                                  // [HID]
  float*    b_arr = a_arr + HID;                                // [HID]
  float*    w3s   = b_arr + HID;                                // [HID]
  int*      ord   = reinterpret_cast<int*>(w3s + HID);          // [HID]
  float*    qs    = reinterpret_cast<float*>(ord + HID);        // [MCAND]
  float*    angs  = qs + MCAND;                                 // [MCAND]
  uint32_t* keyA  = reinterpret_cast<uint32_t*>(angs + MCAND);  // [NITER-1]
  uint32_t* keyB  = keyA + (NITER - 1);                         // [NITER-1]
  float*    musd  = reinterpret_cast<float*>(keyB + (NITER - 1)); // [2]

  const int tid = threadIdx.x;
  const int row = blockIdx.x;
  const float b3v = b3[0];

  // ================= per-row precompute =================
  if (tid < HID) {
    float s0 = states[2 * row], s1 = states[2 * row + 1];
    float a = fmaf(s1, W1[HID + tid], fmaf(s0, W1[tid], b1[tid]));
    float b = W1[2 * HID + tid];
    a_arr[tid] = a;
    b_arr[tid] = b;
    tun[tid]   = -a / b;
    w3s[tid]   = W3[tid];
  }
  if (tid == HID) tsort[HID] = __int_as_float(0x7F800000);  // +inf sentinel
  // PRNG setup: key = jax.random.key(42) => (0,42); partitionable split
  uint32_t k0a, k0b, klA, klB;
  tf2x32(0u, 42u, 0u, 0u, k0a, k0b);
  tf2x32(0u, 42u, 0u, 1u, klA, klB);
  if (tid < NITER - 1) {
    uint32_t ya, yb;
    tf2x32(klA, klB, 0u, (uint32_t)tid, ya, yb);
    keyA[tid] = ya; keyB[tid] = yb;
  }
  __syncthreads();

  // rank-sort knees (stable)
  if (tid < HID) {
    float tme = tun[tid];
    int rank = 0;
#pragma unroll 4
    for (int m = 0; m < HID; ++m) {
      float tm = tun[m];
      rank += (tm < tme) || (tm == tme && m < tid);
    }
    ord[rank]   = tid;
    tsort[rank] = tme;
  }
  __syncthreads();

  // region-0 coefficients (angle -> -inf: active iff b_k < 0), b2 folded in;
  // then per-knee deltas into regions 1..100
  if (tid < HID) {
    float A = b2[tid], B = 0.0f;
#pragma unroll 4
    for (int k = 0; k < HID; ++k) {
      float bk = b_arr[k];
      if (bk < 0.0f) {
        float w = W2[k * HID + tid];
        A = fmaf(w, a_arr[k], A);
        B = fmaf(w, bk, B);
      }
    }
    AB[tid] = make_float2(A, B);
#pragma unroll 4
    for (int r = 0; r < HID; ++r) {
      int k = ord[r];
      float ak = a_arr[k], bk = b_arr[k];
      float w = W2[k * HID + tid];
      w = (bk > 0.0f) ? w : -w;    // crossing t_k upward: b>0 activates, b<0 deactivates
      AB[(r + 1) * HID + tid] = make_float2(w * ak, w * bk);
    }
  }
  __syncthreads();

  // prefix-sum deltas over regions (per-j serial, j-parallel)
  if (tid < HID) {
    float2 acc = AB[tid];
#pragma unroll 4
    for (int r = 1; r < NREG; ++r) {
      float2 d = AB[r * HID + tid];
      acc.x += d.x; acc.y += d.y;
      AB[r * HID + tid] = acc;
    }
  }

  // iteration-0 angles: uniform [0,1)
  if (tid < MCAND)
    angs[tid] = u01_from_bits(jax_bits(k0a, k0b, (uint32_t)(row * MCAND + tid)));
  __syncthreads();

  // ================= CEM loop =================
  const float LO    = __uint_as_float(0xBF7FFFFFu);  // nextafter(-1,0)
  const float SQRT2 = __uint_as_float(0x3FB504F3u);
  const float TWOPI = __uint_as_float(0x40C90FDBu);
  const int lane = tid & 31, wid = tid >> 5;
  const int c   = tid >> 1, half = tid & 1;           // 2 threads per candidate
  const bool cval = (c < MCAND);
  const int cs  = cval ? c : 0;                       // clamped for idle threads

  for (int it = 0; it < NITER - 1; ++it) {
    // ---- candidate eval: ALL threads run this (converged shuffles) ----
    {
      float angle = angs[cs];
      int lo = 0, hi = HID;
#pragma unroll 7
      for (int s = 0; s < 7; ++s) {     // count knees < angle; tsort[100]=+inf
        int mid = (lo + hi) >> 1;
        if (tsort[mid] < angle) lo = mid + 1; else hi = mid;
      }
      const float4* rp = reinterpret_cast<const float4*>(AB + lo * HID + half * (HID / 2));
      const float*  wp = w3s + half * (HID / 2);
      float q0 = 0.f, q1 = 0.f;
#pragma unroll
      for (int jj = 0; jj < HID / 4; ++jj) {
        float4 v = rp[jj];
        float e0 = fmaf(v.y, angle, v.x);
        float e1 = fmaf(v.w, angle, v.z);
        q0 = fmaf(fmaxf(e0, 0.f), wp[2 * jj],     q0);
        q1 = fmaf(fmaxf(e1, 0.f), wp[2 * jj + 1], q1);
      }
      float qp = q0 + q1;
      qp += __shfl_xor_sync(0xffffffffu, qp, 1);      // full warp converged
      if (cval && half == 0) qs[c] = qp + b3v;
    }
    __syncthreads();

    // ---- top-32 stats on warp 0 ----
    if (wid == 0) {
      const bool has2 = lane < (MCAND - 32);
      const float q1v = qs[lane];
      const float q2v = qs[has2 ? 32 + lane : 0];
      int rank1 = 0, rank2 = 0;
#pragma unroll
      for (int cc = 0; cc < MCAND; ++cc) {
        float qv = qs[cc];
        rank1 += (qv > q1v) || (qv == q1v && cc < lane);
        rank2 += (qv > q2v) || (qv == q2v && cc < 32 + lane);
      }
      const bool s1 = rank1 < NTOP;
      const bool s2 = has2 && (rank2 < NTOP);
      float s = (s1 ? q1v : 0.f) + (s2 ? q2v : 0.f);
#pragma unroll
      for (int o = 16; o > 0; o >>= 1) s += __shfl_xor_sync(0xffffffffu, s, o);
      const float mu = s * (1.0f / NTOP);
      float d = (s1 ? (q1v - mu) * (q1v - mu) : 0.f) + (s2 ? (q2v - mu) * (q2v - mu) : 0.f);
#pragma unroll
      for (int o = 16; o > 0; o >>= 1) d += __shfl_xor_sync(0xffffffffu, d, o);
      if (lane == 0) {
        musd[0] = mu;
        musd[1] = sqrtf(d * (1.0f / (NTOP - 1)));
      }
    }
    __syncthreads();

    if (it == NITER - 2) {
      if (tid == 0) out[row] = musd[0] * TWOPI;
      break;
    }

    // ---- sample next angles: N(mu_q, std_q) ----
    if (tid < MCAND) {
      uint32_t bits = jax_bits(keyA[it], keyB[it], (uint32_t)(row * MCAND + tid));
      float u = fmaxf(LO, fmaf(u01_from_bits(bits), 2.0f, LO));
      angs[tid] = fmaf(musd[1], SQRT2 * erfinv_f32(u), musd[0]);
    }
    __syncthreads();
  }
}

extern "C" void kernel_launch(void* const* d_in, const int* in_sizes, int n_in,
                              void* d_out, int out_size) {
  const float* states = (const float*)d_in[0];
  const float* W1     = (const float*)d_in[1];
  const float* b1     = (const float*)d_in[2];
  const float* W2     = (const float*)d_in[3];
  const float* b2     = (const float*)d_in[4];
  const float* W3     = (const float*)d_in[5];
  const float* b3     = (const float*)d_in[6];
  float* out          = (float*)d_out;
  (void)in_sizes; (void)n_in; (void)out_size;

  const size_t SMEM_BYTES =
      sizeof(float2) * NREG * HID +        // AB table
      sizeof(float) * (HID + 1) +          // tsort (+sentinel)
      sizeof(float) * HID * 4 +            // tun, a, b, w3
      sizeof(int) * HID +                  // ord
      sizeof(float) * MCAND * 2 +          // qs, angs
      sizeof(uint32_t) * (NITER - 1) * 2 + // keys
      sizeof(float) * 2 + 64;              // musd + pad

  cudaFuncSetAttribute(cem_kernel, cudaFuncAttributeMaxDynamicSharedMemorySize,
                       (int)SMEM_BYTES);
  cem_kernel<<<NBATCH, TPB, SMEM_BYTES>>>(states, W1, b1, W2, b2, W3, b3, out);
}